// round 13
// baseline (speedup 1.0000x reference)
#include <cuda_runtime.h>
#include <cuda_fp16.h>
#include <cstdint>

#define BATCH 4096
#define ACT   2048
#define DICT  32768
#define K_TOP 64
#define EPS   5e-3f
#define CAND_CAP 256

// ---------------- device scratch (static, no allocations) ----------------
__device__ __half g_Af[(size_t)BATCH * ACT];
__device__ __half g_Bf[(size_t)DICT * ACT];
__device__ __half g_WdecTh[(size_t)DICT * ACT];   // [DICT][ACT] fp16
__device__ __half g_P[(size_t)BATCH * DICT];      // pre_act scratch, fp16 (>=0)
__device__ float  g_vals[BATCH * K_TOP];
__device__ int    g_idxs[BATCH * K_TOP];

// ---------------- prep: fp32 -> fp16 ----------------
__global__ void prep_a_kernel(const float* __restrict__ x,
                              const float* __restrict__ b_dec) {
    size_t i4 = ((size_t)blockIdx.x * blockDim.x + threadIdx.x) * 4;
    float4 v = *(const float4*)&x[i4];
    int c = (int)(i4 & (ACT - 1));
    float4 b = *(const float4*)&b_dec[c];
    __half2* o = (__half2*)&g_Af[i4];
    o[0] = __floats2half2_rn(v.x - b.x, v.y - b.y);
    o[1] = __floats2half2_rn(v.z - b.z, v.w - b.w);
}

__global__ void prep_b_kernel(const float* __restrict__ W) {
    size_t i4 = ((size_t)blockIdx.x * blockDim.x + threadIdx.x) * 4;
    float4 v = *(const float4*)&W[i4];
    __half2* o = (__half2*)&g_Bf[i4];
    o[0] = __floats2half2_rn(v.x, v.y);
    o[1] = __floats2half2_rn(v.z, v.w);
}

// ---------------- transpose W_dec [ACT][DICT] -> g_WdecTh [DICT][ACT] ----
__global__ void transpose_kernel(const float* __restrict__ W) {
    __shared__ float tile[32][33];
    int bx = blockIdx.x * 32;
    int by = blockIdx.y * 32;
    int tx = threadIdx.x, ty = threadIdx.y;
#pragma unroll
    for (int j = 0; j < 32; j += 8)
        tile[ty + j][tx] = W[(size_t)(by + ty + j) * DICT + bx + tx];
    __syncthreads();
#pragma unroll
    for (int j = 0; j < 32; j += 8)
        g_WdecTh[(size_t)(bx + ty + j) * ACT + by + tx] =
            __float2half(tile[tx][ty + j]);
}

// ---------------- encode GEMM -> fp16 pre_act scratch --------------------
// 128x128 tile, BK=64, warp grid 2M x 2N x 2K (split-K in-CTA),
// 3-stage cp.async, 1 sync/k-tile, 1 CTA/SM (256 thr)
#define BM 128
#define BN 128
#define BK 64
#define SSTR 72
#define STAGE_ELEMS (128 * SSTR)
#define NSTAGE 3
#define GEMM_SMEM (NSTAGE * 2 * STAGE_ELEMS * 2)   // 110592 B
#define PST 136
#define REDW 65
// epilogue layout (bytes): red[0 .. 66560), po[66560 .. 101376) -- fits.
#define PO_HALF_OFF 33280          // 66560 / sizeof(__half)

__device__ __forceinline__ void cp16(unsigned saddr, const void* g) {
    asm volatile("cp.async.cg.shared.global [%0], [%1], 16;\n" ::"r"(saddr), "l"(g));
}

#define LDSM4(r, a)                                                          \
    asm volatile(                                                            \
        "ldmatrix.sync.aligned.m8n8.x4.shared.b16 {%0,%1,%2,%3}, [%4];"      \
        : "=r"((r)[0]), "=r"((r)[1]), "=r"((r)[2]), "=r"((r)[3])             \
        : "r"(a))

__device__ __forceinline__ void mma_f16(float* c, const uint32_t* a,
                                        const uint32_t* b) {
    asm volatile(
        "mma.sync.aligned.m16n8k16.row.col.f32.f16.f16.f32 "
        "{%0,%1,%2,%3},{%4,%5,%6,%7},{%8,%9},{%0,%1,%2,%3};\n"
        : "+f"(c[0]), "+f"(c[1]), "+f"(c[2]), "+f"(c[3])
        : "r"(a[0]), "r"(a[1]), "r"(a[2]), "r"(a[3]), "r"(b[0]), "r"(b[1]));
}

__global__ void __launch_bounds__(256, 1)
encode_gemm_kernel(const float* __restrict__ b_enc) {
    extern __shared__ __align__(16) __half sm[];

    const int tid = threadIdx.x;
    const int by = blockIdx.x * BM;
    const int bx = blockIdx.y * BN;
    const int warp = tid >> 5, lane = tid & 31;
    const int wk  = warp >> 2;                // k-half 0/1
    const int wm  = (warp & 1) * 64;          // M group
    const int wn  = ((warp >> 1) & 1) * 64;   // N group
    const int g = lane >> 2, tig = lane & 3;

    const unsigned uS = (unsigned)__cvta_generic_to_shared(sm);

    const int aRow = wm + (lane & 15);
    const int aCol = (lane & 16) >> 1;
    const int bRow = wn + (lane & 7) + ((lane & 16) >> 1);
    const int bCol = lane & 8;

    float acc[4][8][4];
#pragma unroll
    for (int mi = 0; mi < 4; mi++)
#pragma unroll
        for (int ni = 0; ni < 8; ni++)
#pragma unroll
            for (int q = 0; q < 4; q++) acc[mi][ni][q] = 0.f;

    const int KT = ACT / BK;

#define LOAD_STAGE(stage, kt)                                                  \
    {                                                                          \
        const int koff = (kt) * BK;                                            \
        _Pragma("unroll")                                                      \
        for (int r = 0; r < 4; r++) {                                          \
            int id = tid + r * 256;                                            \
            int row = id >> 3;                                                 \
            int ch = (id & 7) * 8;                                             \
            unsigned sa =                                                      \
                (unsigned)(((stage) * 2 * STAGE_ELEMS + row * SSTR + ch) * 2); \
            cp16(uS + sa, &g_Af[(size_t)(by + row) * ACT + koff + ch]);        \
            cp16(uS + sa + STAGE_ELEMS * 2,                                    \
                 &g_Bf[(size_t)(bx + row) * ACT + koff + ch]);                 \
        }                                                                      \
    }

    LOAD_STAGE(0, 0);
    asm volatile("cp.async.commit_group;\n");
    LOAD_STAGE(1, 1);
    asm volatile("cp.async.commit_group;\n");

    int cur = 0, nxt = 2;
    for (int kt = 0; kt < KT; kt++) {
        if (kt + 2 < KT) {
            asm volatile("cp.async.wait_group 1;\n");
        } else {
            asm volatile("cp.async.wait_group 0;\n");
        }
        __syncthreads();

        if (kt + 2 < KT) {
            LOAD_STAGE(nxt, kt + 2);
            asm volatile("cp.async.commit_group;\n");
        }

        const unsigned uA = uS + (unsigned)(cur * 2 * STAGE_ELEMS * 2);
        const unsigned uB = uA + STAGE_ELEMS * 2;
#pragma unroll
        for (int ks = 0; ks < 2; ks++) {
            const int kcol = wk * 32 + ks * 16;
            uint32_t af[4][4];
#pragma unroll
            for (int mi = 0; mi < 4; mi++) {
                unsigned ad =
                    uA + (unsigned)(((aRow + mi * 16) * SSTR + kcol + aCol) * 2);
                LDSM4(af[mi], ad);
            }
            uint32_t bf[8][2];
#pragma unroll
            for (int p = 0; p < 4; p++) {
                unsigned bd =
                    uB + (unsigned)(((bRow + p * 16) * SSTR + kcol + bCol) * 2);
                uint32_t r[4];
                LDSM4(r, bd);
                bf[2 * p][0] = r[0];
                bf[2 * p][1] = r[1];
                bf[2 * p + 1][0] = r[2];
                bf[2 * p + 1][1] = r[3];
            }
#pragma unroll
            for (int ni = 0; ni < 8; ni++)
#pragma unroll
                for (int mi = 0; mi < 4; mi++)
                    mma_f16(acc[mi][ni], af[mi], bf[ni]);
        }
        cur = (cur == 2) ? 0 : cur + 1;
        nxt = (nxt == 2) ? 0 : nxt + 1;
    }

    // ---- epilogue: k-split reduce via smem, then +bias/relu -> fp16 ----
    __syncthreads();
    float* red = (float*)sm;               // bytes [0, 66560)
    __half* po = sm + PO_HALF_OFF;         // bytes [66560, 101376)

    if (wk == 1) {
        const int base = (warp - 4) * (64 * REDW);
#pragma unroll
        for (int mi = 0; mi < 4; mi++) {
            int r = mi * 16 + g;
#pragma unroll
            for (int ni = 0; ni < 8; ni++) {
                int c = ni * 8 + tig * 2;
                red[base + r * REDW + c]           = acc[mi][ni][0];
                red[base + r * REDW + c + 1]       = acc[mi][ni][1];
                red[base + (r + 8) * REDW + c]     = acc[mi][ni][2];
                red[base + (r + 8) * REDW + c + 1] = acc[mi][ni][3];
            }
        }
    }
    __syncthreads();
    if (wk == 0) {
        const int base = warp * (64 * REDW);
#pragma unroll
        for (int mi = 0; mi < 4; mi++) {
            int lr = wm + mi * 16 + g;
            int r = mi * 16 + g;
#pragma unroll
            for (int ni = 0; ni < 8; ni++) {
                int c = ni * 8 + tig * 2;
                int lc = wn + c;
                float be0 = __ldg(&b_enc[bx + lc]);
                float be1 = __ldg(&b_enc[bx + lc + 1]);
                float v0 = acc[mi][ni][0] + red[base + r * REDW + c];
                float v1 = acc[mi][ni][1] + red[base + r * REDW + c + 1];
                float v2 = acc[mi][ni][2] + red[base + (r + 8) * REDW + c];
                float v3 = acc[mi][ni][3] + red[base + (r + 8) * REDW + c + 1];
                *(__half2*)&po[lr * PST + lc] = __floats2half2_rn(
                    fmaxf(v0 + be0, 0.f), fmaxf(v1 + be1, 0.f));
                *(__half2*)&po[(lr + 8) * PST + lc] = __floats2half2_rn(
                    fmaxf(v2 + be0, 0.f), fmaxf(v3 + be1, 0.f));
            }
        }
    }
    __syncthreads();
#pragma unroll
    for (int i = tid; i < 2048; i += 256) {
        int r = i >> 4, ch = (i & 15) * 8;
        uint4 v = *(const uint4*)&po[r * PST + ch];
        *(uint4*)&g_P[(size_t)(by + r) * DICT + bx + ch] = v;
    }
}

// ---------------- per-row top-K in fp16 bit domain -----------------------
#define TPB 1024
#define NCHUNK (DICT / TPB)    // 32

__global__ void __launch_bounds__(TPB, 2) topk_kernel(
    const float* __restrict__ x, const float* __restrict__ W_enc,
    const float* __restrict__ b_enc, const float* __restrict__ b_dec,
    float* __restrict__ z) {
    extern __shared__ __align__(16) unsigned short su16[];   // DICT u16 (64 KB)
    __shared__ unsigned s_selmask[DICT / 32];
    __shared__ float s_x[ACT];
    __shared__ unsigned s_hist[256];
    __shared__ unsigned s_gsum[8];
    __shared__ unsigned s_prefix, s_ub, s_lb;
    __shared__ int s_remaining;
    __shared__ int s_ncand, s_ncert;
    __shared__ int s_cand_idx[CAND_CAP];
    __shared__ double s_cand_val[CAND_CAP];
    __shared__ int s_cntf[NCHUNK * 32];
    __shared__ int s_excl[NCHUNK * 32];
    __shared__ int s_wtot[32], s_wbase[32];

    const unsigned FULL = 0xffffffffu;
    const int row = blockIdx.x;
    const int tid = threadIdx.x;
    const int lane = tid & 31, wid = tid >> 5;
    float* zr = z + (size_t)row * DICT;

    {
        const uint4* gp = (const uint4*)(g_P + (size_t)row * DICT);
        uint4* s4 = (uint4*)su16;
#pragma unroll
        for (int i = tid; i < DICT / 8; i += TPB) s4[i] = gp[i];
    }
    for (int i = tid; i < DICT / 32; i += TPB) s_selmask[i] = 0u;
    if (tid == 0) { s_prefix = 0u; s_remaining = K_TOP; s_ncand = 0; s_ncert = 0; }
    __syncthreads();

#pragma unroll
    for (int shift = 8; shift >= 0; shift -= 8) {
        if (tid < 256) s_hist[tid] = 0u;
        __syncthreads();
        unsigned pfx = s_prefix;
        for (int i = tid; i < DICT; i += TPB) {
            unsigned u = su16[i];
            bool ok = (shift == 8) ? true : ((u >> 8) == (pfx >> 8));
            if (ok) atomicAdd(&s_hist[(u >> shift) & 255u], 1u);
        }
        __syncthreads();
        if (tid < 256) {
            unsigned v = s_hist[tid];
#pragma unroll
            for (int off = 16; off; off >>= 1)
                v += __shfl_down_sync(FULL, v, off);
            if (lane == 0) s_gsum[tid >> 5] = v;
        }
        __syncthreads();
        if (tid == 0) {
            int rem = s_remaining;
            unsigned acc = 0;
            int grp = 7;
            for (; grp > 0; grp--) {
                if (acc + s_gsum[grp] >= (unsigned)rem) break;
                acc += s_gsum[grp];
            }
            int b = grp * 32 + 31;
            for (; b > grp * 32; b--) {
                if (acc + s_hist[b] >= (unsigned)rem) break;
                acc += s_hist[b];
            }
            s_prefix = pfx | ((unsigned)b << shift);
            s_remaining = rem - (int)acc;
        }
        __syncthreads();
    }

    if (tid == 0) {
        float Tf = __half2float(__ushort_as_half((unsigned short)s_prefix));
        float hi = Tf + EPS;
        float lo = Tf - EPS;
        __half hh = __float2half_ru(hi);
        unsigned hb = (unsigned)__half_as_ushort(hh);
        s_ub = (__half2float(hh) > hi) ? hb : hb + 1;
        __half hl = __float2half_ru(fmaxf(lo, 0.f));
        s_lb = (unsigned)__half_as_ushort(hl);
    }
    __syncthreads();
    const unsigned ub = s_ub, lb = s_lb;

    {
        int local_cert = 0;
        for (int i = tid; i < DICT; i += TPB) {
            unsigned u = su16[i];
            if (u >= ub) {
                local_cert++;
            } else if (u >= lb) {
                int p = atomicAdd(&s_ncand, 1);
                if (p < CAND_CAP) s_cand_idx[p] = i;
            }
        }
        atomicAdd(&s_ncert, local_cert);
    }
    __syncthreads();

    const int ncand = min(s_ncand, CAND_CAP);
    const int slots = K_TOP - s_ncert;

    if (ncand > 0) {
        for (int k = tid; k < ACT; k += TPB)
            s_x[k] = x[(size_t)row * ACT + k] - b_dec[k];
        __syncthreads();

        for (int c = wid; c < ncand; c += 32) {
            const int m = s_cand_idx[c];
            const float* w = &W_enc[(size_t)m * ACT];
            double acc = 0.0;
            const int k0 = lane * (ACT / 32);
#pragma unroll 8
            for (int k = k0; k < k0 + ACT / 32; k++)
                acc = fma((double)s_x[k], (double)__ldg(&w[k]), acc);
#pragma unroll
            for (int off = 16; off; off >>= 1)
                acc += __shfl_down_sync(FULL, acc, off);
            if (lane == 0) {
                double v = acc + (double)__ldg(&b_enc[m]);
                s_cand_val[c] = v > 0.0 ? v : 0.0;
            }
        }
        __syncthreads();

        if (tid < ncand) {
            const double vi = s_cand_val[tid];
            const int ii = s_cand_idx[tid];
            int r = 0;
            for (int j = 0; j < ncand; j++) {
                double vj = s_cand_val[j];
                if (vj > vi || (vj == vi && s_cand_idx[j] < ii)) r++;
            }
            if (r < slots) atomicOr(&s_selmask[ii >> 5], 1u << (ii & 31));
        }
        __syncthreads();
    }

#pragma unroll 4
    for (int c = 0; c < NCHUNK; c++) {
        int i = c * TPB + tid;
        bool sel = (su16[i] >= ub) ||
                   ((s_selmask[i >> 5] >> (i & 31)) & 1u);
        unsigned b = __ballot_sync(FULL, sel);
        if (lane == 0) s_cntf[c * 32 + wid] = __popc(b);
    }
    __syncthreads();

    {
        int j = wid * 32 + lane;
        int a = s_cntf[j];
        int s = a;
#pragma unroll
        for (int off = 1; off < 32; off <<= 1) {
            int t = __shfl_up_sync(FULL, s, off);
            if (lane >= off) s += t;
        }
        s_excl[j] = s - a;
        if (lane == 31) s_wtot[wid] = s;
    }
    __syncthreads();
    if (wid == 0) {
        int v = s_wtot[lane];
        int s = v;
#pragma unroll
        for (int off = 1; off < 32; off <<= 1) {
            int t = __shfl_up_sync(FULL, s, off);
            if (lane >= off) s += t;
        }
        s_wbase[lane] = s - v;
    }
    __syncthreads();

    const unsigned lmask = (1u << lane) - 1u;
#pragma unroll 4
    for (int c = 0; c < NCHUNK; c++) {
        int i = c * TPB + tid;
        unsigned u = su16[i];
        bool sel = (u >= ub) || ((s_selmask[i >> 5] >> (i & 31)) & 1u);
        unsigned b = __ballot_sync(FULL, sel);
        float uv = __half2float(__ushort_as_half((unsigned short)u));
        zr[i] = sel ? uv : 0.f;
        if (sel) {
            int j = c * 32 + wid;
            int slot = s_wbase[j >> 5] + s_excl[j] + __popc(b & lmask);
            g_idxs[row * K_TOP + slot] = i;
            g_vals[row * K_TOP + slot] = uv;
        }
    }
}

// ---------------- decode: x_hat = sum_k vals * W_decTh[idx] + b_dec ------
__global__ void __launch_bounds__(256)
decode_kernel(const float* __restrict__ b_dec, float* __restrict__ xhat) {
    __shared__ int s_idx[K_TOP];
    __shared__ float s_val[K_TOP];
    const int row = blockIdx.x;
    const int tid = threadIdx.x;
    if (tid < K_TOP) {
        s_idx[tid] = g_idxs[row * K_TOP + tid];
        s_val[tid] = g_vals[row * K_TOP + tid];
    }
    __syncthreads();
    const int d0 = tid * 8;
    float a[8];
#pragma unroll
    for (int j = 0; j < 8; j += 4) {
        float4 b4 = *(const float4*)&b_dec[d0 + j];
        a[j] = b4.x; a[j + 1] = b4.y; a[j + 2] = b4.z; a[j + 3] = b4.w;
    }
#pragma unroll 4
    for (int k = 0; k < K_TOP; k++) {
        const __half2* w = (const __half2*)&g_WdecTh[(size_t)s_idx[k] * ACT + d0];
        float v = s_val[k];
#pragma unroll
        for (int j = 0; j < 4; j++) {
            float2 f = __half22float2(w[j]);
            a[2 * j]     += v * f.x;
            a[2 * j + 1] += v * f.y;
        }
    }
    *(float4*)&xhat[(size_t)row * ACT + d0] =
        make_float4(a[0], a[1], a[2], a[3]);
    *(float4*)&xhat[(size_t)row * ACT + d0 + 4] =
        make_float4(a[4], a[5], a[6], a[7]);
}

// ---------------- launch ----------------
extern "C" void kernel_launch(void* const* d_in, const int* in_sizes, int n_in,
                              void* d_out, int out_size) {
    (void)in_sizes; (void)n_in; (void)out_size;
    const float* x     = (const float*)d_in[0];
    const float* W_enc = (const float*)d_in[1];
    const float* b_enc = (const float*)d_in[2];
    const float* W_dec = (const float*)d_in[3];
    const float* b_dec = (const float*)d_in[4];
    float* xhat = (float*)d_out;
    float* z    = xhat + (size_t)BATCH * ACT;

    prep_a_kernel<<<(BATCH * (size_t)ACT) / 1024, 256>>>(x, b_dec);
    prep_b_kernel<<<(DICT * (size_t)ACT) / 1024, 256>>>(W_enc);
    transpose_kernel<<<dim3(DICT / 32, ACT / 32), dim3(32, 8)>>>(W_dec);

    cudaFuncSetAttribute(encode_gemm_kernel,
                         cudaFuncAttributeMaxDynamicSharedMemorySize, GEMM_SMEM);
    encode_gemm_kernel<<<dim3(BATCH / BM, DICT / BN), 256, GEMM_SMEM>>>(b_enc);

    cudaFuncSetAttribute(topk_kernel,
                         cudaFuncAttributeMaxDynamicSharedMemorySize, DICT * 2);
    topk_kernel<<<BATCH, TPB, DICT * 2>>>(x, W_enc, b_enc, b_dec, z);

    decode_kernel<<<BATCH, 256>>>(b_dec, xhat);
}

// round 14
// speedup vs baseline: 1.2451x; 1.2451x over previous
#include <cuda_runtime.h>
#include <cuda_fp16.h>
#include <cstdint>

#define BATCH 4096
#define ACT   2048
#define DICT  32768
#define K_TOP 64
#define EPS   5e-3f
#define CAND_CAP 256

// ---------------- device scratch (static, no allocations) ----------------
__device__ __half g_Af[(size_t)BATCH * ACT];
__device__ __half g_Bf[(size_t)DICT * ACT];
__device__ __half g_WdecTh[(size_t)DICT * ACT];   // [DICT][ACT] fp16
__device__ __half g_P[(size_t)BATCH * DICT];      // pre_act scratch, fp16 (>=0)

// ---------------- prep: fp32 -> fp16 ----------------
__global__ void prep_a_kernel(const float* __restrict__ x,
                              const float* __restrict__ b_dec) {
    size_t i4 = ((size_t)blockIdx.x * blockDim.x + threadIdx.x) * 4;
    float4 v = *(const float4*)&x[i4];
    int c = (int)(i4 & (ACT - 1));
    float4 b = *(const float4*)&b_dec[c];
    __half2* o = (__half2*)&g_Af[i4];
    o[0] = __floats2half2_rn(v.x - b.x, v.y - b.y);
    o[1] = __floats2half2_rn(v.z - b.z, v.w - b.w);
}

__global__ void prep_b_kernel(const float* __restrict__ W) {
    size_t i4 = ((size_t)blockIdx.x * blockDim.x + threadIdx.x) * 4;
    float4 v = *(const float4*)&W[i4];
    __half2* o = (__half2*)&g_Bf[i4];
    o[0] = __floats2half2_rn(v.x, v.y);
    o[1] = __floats2half2_rn(v.z, v.w);
}

// ---------------- transpose W_dec [ACT][DICT] -> g_WdecTh [DICT][ACT] ----
__global__ void transpose_kernel(const float* __restrict__ W) {
    __shared__ float tile[32][33];
    int bx = blockIdx.x * 32;
    int by = blockIdx.y * 32;
    int tx = threadIdx.x, ty = threadIdx.y;
#pragma unroll
    for (int j = 0; j < 32; j += 8)
        tile[ty + j][tx] = W[(size_t)(by + ty + j) * DICT + bx + tx];
    __syncthreads();
#pragma unroll
    for (int j = 0; j < 32; j += 8)
        g_WdecTh[(size_t)(bx + ty + j) * ACT + by + tx] =
            __float2half(tile[tx][ty + j]);
}

// ---------------- encode GEMM -> fp16 pre_act scratch (R11 config) -------
#define BM 128
#define BN 128
#define BK 64
#define SSTR 72
#define STAGE_ELEMS (128 * SSTR)
#define NSTAGE 3
#define GEMM_SMEM (NSTAGE * 2 * STAGE_ELEMS * 2)   // 110592 B; x2 CTA = 216KB
#define PST 136

__device__ __forceinline__ void cp16(unsigned saddr, const void* g) {
    asm volatile("cp.async.cg.shared.global [%0], [%1], 16;\n" ::"r"(saddr), "l"(g));
}

#define LDSM4(r, a)                                                          \
    asm volatile(                                                            \
        "ldmatrix.sync.aligned.m8n8.x4.shared.b16 {%0,%1,%2,%3}, [%4];"      \
        : "=r"((r)[0]), "=r"((r)[1]), "=r"((r)[2]), "=r"((r)[3])             \
        : "r"(a))

__device__ __forceinline__ void mma_f16(float* c, const uint32_t* a,
                                        const uint32_t* b) {
    asm volatile(
        "mma.sync.aligned.m16n8k16.row.col.f32.f16.f16.f32 "
        "{%0,%1,%2,%3},{%4,%5,%6,%7},{%8,%9},{%0,%1,%2,%3};\n"
        : "+f"(c[0]), "+f"(c[1]), "+f"(c[2]), "+f"(c[3])
        : "r"(a[0]), "r"(a[1]), "r"(a[2]), "r"(a[3]), "r"(b[0]), "r"(b[1]));
}

__global__ void __launch_bounds__(256, 2)
encode_gemm_kernel(const float* __restrict__ b_enc) {
    extern __shared__ __align__(16) __half sm[];

    const int tid = threadIdx.x;
    const int by = blockIdx.x * BM;
    const int bx = blockIdx.y * BN;
    const int warp = tid >> 5, lane = tid & 31;
    const int wm = (warp & 3) * 32;
    const int wn = (warp >> 2) * 64;
    const int g = lane >> 2, tig = lane & 3;

    const unsigned uS = (unsigned)__cvta_generic_to_shared(sm);

    const int aRow = wm + (lane & 15);
    const int aCol = (lane & 16) >> 1;
    const int bRow = wn + (lane & 7) + ((lane & 16) >> 1);
    const int bCol = lane & 8;

    float acc[2][8][4];
#pragma unroll
    for (int mi = 0; mi < 2; mi++)
#pragma unroll
        for (int ni = 0; ni < 8; ni++)
#pragma unroll
            for (int q = 0; q < 4; q++) acc[mi][ni][q] = 0.f;

    const int KT = ACT / BK;

#define LOAD_STAGE(stage, kt)                                                  \
    {                                                                          \
        const int koff = (kt) * BK;                                            \
        _Pragma("unroll")                                                      \
        for (int r = 0; r < 4; r++) {                                          \
            int id = tid + r * 256;                                            \
            int row = id >> 3;                                                 \
            int ch = (id & 7) * 8;                                             \
            unsigned sa =                                                      \
                (unsigned)(((stage) * 2 * STAGE_ELEMS + row * SSTR + ch) * 2); \
            cp16(uS + sa, &g_Af[(size_t)(by + row) * ACT + koff + ch]);        \
            cp16(uS + sa + STAGE_ELEMS * 2,                                    \
                 &g_Bf[(size_t)(bx + row) * ACT + koff + ch]);                 \
        }                                                                      \
    }

    LOAD_STAGE(0, 0);
    asm volatile("cp.async.commit_group;\n");
    LOAD_STAGE(1, 1);
    asm volatile("cp.async.commit_group;\n");

    int cur = 0, nxt = 2;
    for (int kt = 0; kt < KT; kt++) {
        if (kt + 2 < KT) {
            asm volatile("cp.async.wait_group 1;\n");
        } else {
            asm volatile("cp.async.wait_group 0;\n");
        }
        __syncthreads();

        if (kt + 2 < KT) {
            LOAD_STAGE(nxt, kt + 2);
            asm volatile("cp.async.commit_group;\n");
        }

        const unsigned uA = uS + (unsigned)(cur * 2 * STAGE_ELEMS * 2);
        const unsigned uB = uA + STAGE_ELEMS * 2;
#pragma unroll
        for (int ks = 0; ks < 4; ks++) {
            const int kcol = ks * 16;
            uint32_t af[2][4];
#pragma unroll
            for (int mi = 0; mi < 2; mi++) {
                unsigned ad =
                    uA + (unsigned)(((aRow + mi * 16) * SSTR + kcol + aCol) * 2);
                LDSM4(af[mi], ad);
            }
            uint32_t bf[8][2];
#pragma unroll
            for (int p = 0; p < 4; p++) {
                unsigned bd =
                    uB + (unsigned)(((bRow + p * 16) * SSTR + kcol + bCol) * 2);
                uint32_t r[4];
                LDSM4(r, bd);
                bf[2 * p][0] = r[0];
                bf[2 * p][1] = r[1];
                bf[2 * p + 1][0] = r[2];
                bf[2 * p + 1][1] = r[3];
            }
#pragma unroll
            for (int ni = 0; ni < 8; ni++)
#pragma unroll
                for (int mi = 0; mi < 2; mi++)
                    mma_f16(acc[mi][ni], af[mi], bf[ni]);
        }
        cur = (cur == 2) ? 0 : cur + 1;
        nxt = (nxt == 2) ? 0 : nxt + 1;
    }

    __syncthreads();
#pragma unroll
    for (int mi = 0; mi < 2; mi++) {
        int lr = wm + mi * 16 + g;
#pragma unroll
        for (int ni = 0; ni < 8; ni++) {
            int lc = wn + ni * 8 + tig * 2;
            float be0 = __ldg(&b_enc[bx + lc]);
            float be1 = __ldg(&b_enc[bx + lc + 1]);
            *(__half2*)&sm[lr * PST + lc] = __floats2half2_rn(
                fmaxf(acc[mi][ni][0] + be0, 0.f), fmaxf(acc[mi][ni][1] + be1, 0.f));
            *(__half2*)&sm[(lr + 8) * PST + lc] = __floats2half2_rn(
                fmaxf(acc[mi][ni][2] + be0, 0.f), fmaxf(acc[mi][ni][3] + be1, 0.f));
        }
    }
    __syncthreads();
#pragma unroll
    for (int i = tid; i < 2048; i += 256) {
        int r = i >> 4, ch = (i & 15) * 8;
        uint4 v = *(const uint4*)&sm[r * PST + ch];
        *(uint4*)&g_P[(size_t)(by + r) * DICT + bx + ch] = v;
    }
}

// ------- fused per-row top-K (fp16 bit domain) + sparse decode -----------
#define TPB 1024
#define NCHUNK (DICT / TPB)    // 32

__global__ void __launch_bounds__(TPB, 2) topk_decode_kernel(
    const float* __restrict__ x, const float* __restrict__ W_enc,
    const float* __restrict__ b_enc, const float* __restrict__ b_dec,
    float* __restrict__ z, float* __restrict__ xhat) {
    extern __shared__ __align__(16) unsigned short su16[];   // DICT u16 (64 KB)
    __shared__ unsigned s_selmask[DICT / 32];
    __shared__ float s_x[ACT];
    __shared__ unsigned s_hist[256];
    __shared__ unsigned s_gsum[8];
    __shared__ unsigned s_prefix, s_ub, s_lb;
    __shared__ int s_remaining;
    __shared__ int s_ncand, s_ncert;
    __shared__ int s_cand_idx[CAND_CAP];
    __shared__ double s_cand_val[CAND_CAP];
    __shared__ int s_cntf[NCHUNK * 32];
    __shared__ int s_excl[NCHUNK * 32];
    __shared__ int s_wtot[32], s_wbase[32];
    __shared__ int s_didx[K_TOP];
    __shared__ float s_dval[K_TOP];

    const unsigned FULL = 0xffffffffu;
    const int row = blockIdx.x;
    const int tid = threadIdx.x;
    const int lane = tid & 31, wid = tid >> 5;
    float* zr = z + (size_t)row * DICT;

    {
        const uint4* gp = (const uint4*)(g_P + (size_t)row * DICT);
        uint4* s4 = (uint4*)su16;
#pragma unroll
        for (int i = tid; i < DICT / 8; i += TPB) s4[i] = gp[i];
    }
    for (int i = tid; i < DICT / 32; i += TPB) s_selmask[i] = 0u;
    if (tid == 0) { s_prefix = 0u; s_remaining = K_TOP; s_ncand = 0; s_ncert = 0; }
    __syncthreads();

#pragma unroll
    for (int shift = 8; shift >= 0; shift -= 8) {
        if (tid < 256) s_hist[tid] = 0u;
        __syncthreads();
        unsigned pfx = s_prefix;
        for (int i = tid; i < DICT; i += TPB) {
            unsigned u = su16[i];
            bool ok = (shift == 8) ? true : ((u >> 8) == (pfx >> 8));
            if (ok) atomicAdd(&s_hist[(u >> shift) & 255u], 1u);
        }
        __syncthreads();
        if (tid < 256) {
            unsigned v = s_hist[tid];
#pragma unroll
            for (int off = 16; off; off >>= 1)
                v += __shfl_down_sync(FULL, v, off);
            if (lane == 0) s_gsum[tid >> 5] = v;
        }
        __syncthreads();
        if (tid == 0) {
            int rem = s_remaining;
            unsigned acc = 0;
            int grp = 7;
            for (; grp > 0; grp--) {
                if (acc + s_gsum[grp] >= (unsigned)rem) break;
                acc += s_gsum[grp];
            }
            int b = grp * 32 + 31;
            for (; b > grp * 32; b--) {
                if (acc + s_hist[b] >= (unsigned)rem) break;
                acc += s_hist[b];
            }
            s_prefix = pfx | ((unsigned)b << shift);
            s_remaining = rem - (int)acc;
        }
        __syncthreads();
    }

    if (tid == 0) {
        float Tf = __half2float(__ushort_as_half((unsigned short)s_prefix));
        float hi = Tf + EPS;
        float lo = Tf - EPS;
        __half hh = __float2half_ru(hi);
        unsigned hb = (unsigned)__half_as_ushort(hh);
        s_ub = (__half2float(hh) > hi) ? hb : hb + 1;
        __half hl = __float2half_ru(fmaxf(lo, 0.f));
        s_lb = (unsigned)__half_as_ushort(hl);
    }
    __syncthreads();
    const unsigned ub = s_ub, lb = s_lb;

    {
        int local_cert = 0;
        for (int i = tid; i < DICT; i += TPB) {
            unsigned u = su16[i];
            if (u >= ub) {
                local_cert++;
            } else if (u >= lb) {
                int p = atomicAdd(&s_ncand, 1);
                if (p < CAND_CAP) s_cand_idx[p] = i;
            }
        }
        atomicAdd(&s_ncert, local_cert);
    }
    __syncthreads();

    const int ncand = min(s_ncand, CAND_CAP);
    const int slots = K_TOP - s_ncert;

    if (ncand > 0) {
        for (int k = tid; k < ACT; k += TPB)
            s_x[k] = x[(size_t)row * ACT + k] - b_dec[k];
        __syncthreads();

        for (int c = wid; c < ncand; c += 32) {
            const int m = s_cand_idx[c];
            const float* w = &W_enc[(size_t)m * ACT];
            double acc = 0.0;
            const int k0 = lane * (ACT / 32);
#pragma unroll 8
            for (int k = k0; k < k0 + ACT / 32; k++)
                acc = fma((double)s_x[k], (double)__ldg(&w[k]), acc);
#pragma unroll
            for (int off = 16; off; off >>= 1)
                acc += __shfl_down_sync(FULL, acc, off);
            if (lane == 0) {
                double v = acc + (double)__ldg(&b_enc[m]);
                s_cand_val[c] = v > 0.0 ? v : 0.0;
            }
        }
        __syncthreads();

        if (tid < ncand) {
            const double vi = s_cand_val[tid];
            const int ii = s_cand_idx[tid];
            int r = 0;
            for (int j = 0; j < ncand; j++) {
                double vj = s_cand_val[j];
                if (vj > vi || (vj == vi && s_cand_idx[j] < ii)) r++;
            }
            if (r < slots) atomicOr(&s_selmask[ii >> 5], 1u << (ii & 31));
        }
        __syncthreads();
    }

#pragma unroll 4
    for (int c = 0; c < NCHUNK; c++) {
        int i = c * TPB + tid;
        bool sel = (su16[i] >= ub) ||
                   ((s_selmask[i >> 5] >> (i & 31)) & 1u);
        unsigned b = __ballot_sync(FULL, sel);
        if (lane == 0) s_cntf[c * 32 + wid] = __popc(b);
    }
    __syncthreads();

    {
        int j = wid * 32 + lane;
        int a = s_cntf[j];
        int s = a;
#pragma unroll
        for (int off = 1; off < 32; off <<= 1) {
            int t = __shfl_up_sync(FULL, s, off);
            if (lane >= off) s += t;
        }
        s_excl[j] = s - a;
        if (lane == 31) s_wtot[wid] = s;
    }
    __syncthreads();
    if (wid == 0) {
        int v = s_wtot[lane];
        int s = v;
#pragma unroll
        for (int off = 1; off < 32; off <<= 1) {
            int t = __shfl_up_sync(FULL, s, off);
            if (lane >= off) s += t;
        }
        s_wbase[lane] = s - v;
    }
    __syncthreads();

    // D2: write z + fill smem (idx,val) lists
    const unsigned lmask = (1u << lane) - 1u;
#pragma unroll 4
    for (int c = 0; c < NCHUNK; c++) {
        int i = c * TPB + tid;
        unsigned u = su16[i];
        bool sel = (u >= ub) || ((s_selmask[i >> 5] >> (i & 31)) & 1u);
        unsigned b = __ballot_sync(FULL, sel);
        float uv = __half2float(__ushort_as_half((unsigned short)u));
        zr[i] = sel ? uv : 0.f;
        if (sel) {
            int j = c * 32 + wid;
            int slot = s_wbase[j >> 5] + s_excl[j] + __popc(b & lmask);
            s_didx[slot] = i;
            s_dval[slot] = uv;
        }
    }
    __syncthreads();

    // ---- fused decode: xhat[row] = sum_k val_k * W_decTh[idx_k] + b_dec
    {
        const int d0 = tid * 2;   // 2 output dims per thread
        float a0 = b_dec[d0];
        float a1 = b_dec[d0 + 1];
#pragma unroll 4
        for (int k = 0; k < K_TOP; k++) {
            const __half2 w =
                *(const __half2*)&g_WdecTh[(size_t)s_didx[k] * ACT + d0];
            float v = s_dval[k];
            float2 f = __half22float2(w);
            a0 += v * f.x;
            a1 += v * f.y;
        }
        *(float2*)&xhat[(size_t)row * ACT + d0] = make_float2(a0, a1);
    }
}

// ---------------- launch ----------------
extern "C" void kernel_launch(void* const* d_in, const int* in_sizes, int n_in,
                              void* d_out, int out_size) {
    (void)in_sizes; (void)n_in; (void)out_size;
    const float* x     = (const float*)d_in[0];
    const float* W_enc = (const float*)d_in[1];
    const float* b_enc = (const float*)d_in[2];
    const float* W_dec = (const float*)d_in[3];
    const float* b_dec = (const float*)d_in[4];
    float* xhat = (float*)d_out;
    float* z    = xhat + (size_t)BATCH * ACT;

    prep_a_kernel<<<(BATCH * (size_t)ACT) / 1024, 256>>>(x, b_dec);
    prep_b_kernel<<<(DICT * (size_t)ACT) / 1024, 256>>>(W_enc);
    transpose_kernel<<<dim3(DICT / 32, ACT / 32), dim3(32, 8)>>>(W_dec);

    cudaFuncSetAttribute(encode_gemm_kernel,
                         cudaFuncAttributeMaxDynamicSharedMemorySize, GEMM_SMEM);
    encode_gemm_kernel<<<dim3(BATCH / BM, DICT / BN), 256, GEMM_SMEM>>>(b_enc);

    cudaFuncSetAttribute(topk_decode_kernel,
                         cudaFuncAttributeMaxDynamicSharedMemorySize, DICT * 2);
    topk_decode_kernel<<<BATCH, TPB, DICT * 2>>>(x, W_enc, b_enc, b_dec, z, xhat);
}

// round 15
// speedup vs baseline: 1.2596x; 1.0117x over previous
#include <cuda_runtime.h>
#include <cuda_fp16.h>
#include <cstdint>

#define BATCH 4096
#define ACT   2048
#define DICT  32768
#define K_TOP 64
#define EPS   5e-3f
#define CAND_CAP 256

// ---------------- device scratch (static, no allocations) ----------------
__device__ __half g_Af[(size_t)BATCH * ACT];
__device__ __half g_Bf[(size_t)DICT * ACT];
__device__ __half g_WdecTh[(size_t)DICT * ACT];   // [DICT][ACT] fp16
__device__ __half g_P[(size_t)BATCH * DICT];      // pre_act scratch, fp16 (>=0)
__device__ float  g_vals[BATCH * K_TOP];
__device__ int    g_idxs[BATCH * K_TOP];

// ---------------- prep: fp32 -> fp16 ----------------
__global__ void prep_a_kernel(const float* __restrict__ x,
                              const float* __restrict__ b_dec) {
    size_t i4 = ((size_t)blockIdx.x * blockDim.x + threadIdx.x) * 4;
    float4 v = *(const float4*)&x[i4];
    int c = (int)(i4 & (ACT - 1));
    float4 b = *(const float4*)&b_dec[c];
    __half2* o = (__half2*)&g_Af[i4];
    o[0] = __floats2half2_rn(v.x - b.x, v.y - b.y);
    o[1] = __floats2half2_rn(v.z - b.z, v.w - b.w);
}

__global__ void prep_b_kernel(const float* __restrict__ W) {
    size_t i4 = ((size_t)blockIdx.x * blockDim.x + threadIdx.x) * 4;
    float4 v = *(const float4*)&W[i4];
    __half2* o = (__half2*)&g_Bf[i4];
    o[0] = __floats2half2_rn(v.x, v.y);
    o[1] = __floats2half2_rn(v.z, v.w);
}

// ---------------- transpose W_dec [ACT][DICT] -> g_WdecTh [DICT][ACT] ----
__global__ void transpose_kernel(const float* __restrict__ W) {
    __shared__ float tile[32][33];
    int bx = blockIdx.x * 32;
    int by = blockIdx.y * 32;
    int tx = threadIdx.x, ty = threadIdx.y;
#pragma unroll
    for (int j = 0; j < 32; j += 8)
        tile[ty + j][tx] = W[(size_t)(by + ty + j) * DICT + bx + tx];
    __syncthreads();
#pragma unroll
    for (int j = 0; j < 32; j += 8)
        g_WdecTh[(size_t)(bx + ty + j) * ACT + by + tx] =
            __float2half(tile[tx][ty + j]);
}

// ---------------- encode GEMM -> fp16 pre_act scratch (R11 config) -------
#define BM 128
#define BN 128
#define BK 64
#define SSTR 72
#define STAGE_ELEMS (128 * SSTR)
#define NSTAGE 3
#define GEMM_SMEM (NSTAGE * 2 * STAGE_ELEMS * 2)   // 110592 B; x2 CTA = 216KB
#define PST 136

__device__ __forceinline__ void cp16(unsigned saddr, const void* g) {
    asm volatile("cp.async.cg.shared.global [%0], [%1], 16;\n" ::"r"(saddr), "l"(g));
}

#define LDSM4(r, a)                                                          \
    asm volatile(                                                            \
        "ldmatrix.sync.aligned.m8n8.x4.shared.b16 {%0,%1,%2,%3}, [%4];"      \
        : "=r"((r)[0]), "=r"((r)[1]), "=r"((r)[2]), "=r"((r)[3])             \
        : "r"(a))

__device__ __forceinline__ void mma_f16(float* c, const uint32_t* a,
                                        const uint32_t* b) {
    asm volatile(
        "mma.sync.aligned.m16n8k16.row.col.f32.f16.f16.f32 "
        "{%0,%1,%2,%3},{%4,%5,%6,%7},{%8,%9},{%0,%1,%2,%3};\n"
        : "+f"(c[0]), "+f"(c[1]), "+f"(c[2]), "+f"(c[3])
        : "r"(a[0]), "r"(a[1]), "r"(a[2]), "r"(a[3]), "r"(b[0]), "r"(b[1]));
}

__global__ void __launch_bounds__(256, 2)
encode_gemm_kernel(const float* __restrict__ b_enc) {
    extern __shared__ __align__(16) __half sm[];

    const int tid = threadIdx.x;
    const int by = blockIdx.x * BM;
    const int bx = blockIdx.y * BN;
    const int warp = tid >> 5, lane = tid & 31;
    const int wm = (warp & 3) * 32;
    const int wn = (warp >> 2) * 64;
    const int g = lane >> 2, tig = lane & 3;

    const unsigned uS = (unsigned)__cvta_generic_to_shared(sm);

    const int aRow = wm + (lane & 15);
    const int aCol = (lane & 16) >> 1;
    const int bRow = wn + (lane & 7) + ((lane & 16) >> 1);
    const int bCol = lane & 8;

    float acc[2][8][4];
#pragma unroll
    for (int mi = 0; mi < 2; mi++)
#pragma unroll
        for (int ni = 0; ni < 8; ni++)
#pragma unroll
            for (int q = 0; q < 4; q++) acc[mi][ni][q] = 0.f;

    const int KT = ACT / BK;

#define LOAD_STAGE(stage, kt)                                                  \
    {                                                                          \
        const int koff = (kt) * BK;                                            \
        _Pragma("unroll")                                                      \
        for (int r = 0; r < 4; r++) {                                          \
            int id = tid + r * 256;                                            \
            int row = id >> 3;                                                 \
            int ch = (id & 7) * 8;                                             \
            unsigned sa =                                                      \
                (unsigned)(((stage) * 2 * STAGE_ELEMS + row * SSTR + ch) * 2); \
            cp16(uS + sa, &g_Af[(size_t)(by + row) * ACT + koff + ch]);        \
            cp16(uS + sa + STAGE_ELEMS * 2,                                    \
                 &g_Bf[(size_t)(bx + row) * ACT + koff + ch]);                 \
        }                                                                      \
    }

    LOAD_STAGE(0, 0);
    asm volatile("cp.async.commit_group;\n");
    LOAD_STAGE(1, 1);
    asm volatile("cp.async.commit_group;\n");

    int cur = 0, nxt = 2;
    for (int kt = 0; kt < KT; kt++) {
        if (kt + 2 < KT) {
            asm volatile("cp.async.wait_group 1;\n");
        } else {
            asm volatile("cp.async.wait_group 0;\n");
        }
        __syncthreads();

        if (kt + 2 < KT) {
            LOAD_STAGE(nxt, kt + 2);
            asm volatile("cp.async.commit_group;\n");
        }

        const unsigned uA = uS + (unsigned)(cur * 2 * STAGE_ELEMS * 2);
        const unsigned uB = uA + STAGE_ELEMS * 2;
#pragma unroll
        for (int ks = 0; ks < 4; ks++) {
            const int kcol = ks * 16;
            uint32_t af[2][4];
#pragma unroll
            for (int mi = 0; mi < 2; mi++) {
                unsigned ad =
                    uA + (unsigned)(((aRow + mi * 16) * SSTR + kcol + aCol) * 2);
                LDSM4(af[mi], ad);
            }
            uint32_t bf[8][2];
#pragma unroll
            for (int p = 0; p < 4; p++) {
                unsigned bd =
                    uB + (unsigned)(((bRow + p * 16) * SSTR + kcol + bCol) * 2);
                uint32_t r[4];
                LDSM4(r, bd);
                bf[2 * p][0] = r[0];
                bf[2 * p][1] = r[1];
                bf[2 * p + 1][0] = r[2];
                bf[2 * p + 1][1] = r[3];
            }
#pragma unroll
            for (int ni = 0; ni < 8; ni++)
#pragma unroll
                for (int mi = 0; mi < 2; mi++)
                    mma_f16(acc[mi][ni], af[mi], bf[ni]);
        }
        cur = (cur == 2) ? 0 : cur + 1;
        nxt = (nxt == 2) ? 0 : nxt + 1;
    }

    __syncthreads();
#pragma unroll
    for (int mi = 0; mi < 2; mi++) {
        int lr = wm + mi * 16 + g;
#pragma unroll
        for (int ni = 0; ni < 8; ni++) {
            int lc = wn + ni * 8 + tig * 2;
            float be0 = __ldg(&b_enc[bx + lc]);
            float be1 = __ldg(&b_enc[bx + lc + 1]);
            *(__half2*)&sm[lr * PST + lc] = __floats2half2_rn(
                fmaxf(acc[mi][ni][0] + be0, 0.f), fmaxf(acc[mi][ni][1] + be1, 0.f));
            *(__half2*)&sm[(lr + 8) * PST + lc] = __floats2half2_rn(
                fmaxf(acc[mi][ni][2] + be0, 0.f), fmaxf(acc[mi][ni][3] + be1, 0.f));
        }
    }
    __syncthreads();
#pragma unroll
    for (int i = tid; i < 2048; i += 256) {
        int r = i >> 4, ch = (i & 15) * 8;
        uint4 v = *(const uint4*)&sm[r * PST + ch];
        *(uint4*)&g_P[(size_t)(by + r) * DICT + bx + ch] = v;
    }
}

// ---------------- per-row top-K in fp16 bit domain -----------------------
// zero-skip: ~50% of pre_act is exactly 0 (relu); bucket-0 atomics were a
// same-address serialization hotspot and bucket 0 is never needed.
#define TPB 1024
#define NCHUNK (DICT / TPB)    // 32

__global__ void __launch_bounds__(TPB, 2) topk_kernel(
    const float* __restrict__ x, const float* __restrict__ W_enc,
    const float* __restrict__ b_enc, const float* __restrict__ b_dec,
    float* __restrict__ z) {
    extern __shared__ __align__(16) unsigned short su16[];   // DICT u16 (64 KB)
    __shared__ unsigned s_selmask[DICT / 32];
    __shared__ float s_x[ACT];
    __shared__ unsigned s_hist[256];
    __shared__ unsigned s_gsum[8];
    __shared__ unsigned s_prefix, s_ub, s_lb;
    __shared__ int s_remaining;
    __shared__ int s_ncand, s_ncert;
    __shared__ int s_cand_idx[CAND_CAP];
    __shared__ double s_cand_val[CAND_CAP];
    __shared__ int s_cntf[NCHUNK * 32];
    __shared__ int s_excl[NCHUNK * 32];
    __shared__ int s_wtot[32], s_wbase[32];

    const unsigned FULL = 0xffffffffu;
    const int row = blockIdx.x;
    const int tid = threadIdx.x;
    const int lane = tid & 31, wid = tid >> 5;
    float* zr = z + (size_t)row * DICT;

    {
        const uint4* gp = (const uint4*)(g_P + (size_t)row * DICT);
        uint4* s4 = (uint4*)su16;
#pragma unroll
        for (int i = tid; i < DICT / 8; i += TPB) s4[i] = gp[i];
    }
    for (int i = tid; i < DICT / 32; i += TPB) s_selmask[i] = 0u;
    if (tid == 0) { s_prefix = 0u; s_remaining = K_TOP; s_ncand = 0; s_ncert = 0; }
    __syncthreads();

    // 2-round radix select over 16-bit keys; zeros skipped (never needed)
#pragma unroll
    for (int shift = 8; shift >= 0; shift -= 8) {
        if (tid < 256) s_hist[tid] = 0u;
        __syncthreads();
        unsigned pfx = s_prefix;
        for (int i = tid; i < DICT; i += TPB) {
            unsigned u = su16[i];
            bool ok = (u != 0u) &&
                      ((shift == 8) ? true : ((u >> 8) == (pfx >> 8)));
            if (ok) atomicAdd(&s_hist[(u >> shift) & 255u], 1u);
        }
        __syncthreads();
        if (tid < 256) {
            unsigned v = s_hist[tid];
#pragma unroll
            for (int off = 16; off; off >>= 1)
                v += __shfl_down_sync(FULL, v, off);
            if (lane == 0) s_gsum[tid >> 5] = v;
        }
        __syncthreads();
        if (tid == 0) {
            int rem = s_remaining;
            unsigned acc = 0;
            int grp = 7;
            for (; grp > 0; grp--) {
                if (acc + s_gsum[grp] >= (unsigned)rem) break;
                acc += s_gsum[grp];
            }
            int b = grp * 32 + 31;
            for (; b > grp * 32; b--) {
                if (acc + s_hist[b] >= (unsigned)rem) break;
                acc += s_hist[b];
            }
            s_prefix = pfx | ((unsigned)b << shift);
            s_remaining = rem - (int)acc;
        }
        __syncthreads();
    }

    if (tid == 0) {
        float Tf = __half2float(__ushort_as_half((unsigned short)s_prefix));
        float hi = Tf + EPS;
        float lo = Tf - EPS;
        __half hh = __float2half_ru(hi);
        unsigned hb = (unsigned)__half_as_ushort(hh);
        s_ub = (__half2float(hh) > hi) ? hb : hb + 1;
        __half hl = __float2half_ru(fmaxf(lo, 0.f));
        s_lb = (unsigned)__half_as_ushort(hl);
    }
    __syncthreads();
    const unsigned ub = s_ub, lb = s_lb;

    {
        int local_cert = 0;
        for (int i = tid; i < DICT; i += TPB) {
            unsigned u = su16[i];
            if (u >= ub) {
                local_cert++;
            } else if (u >= lb) {
                int p = atomicAdd(&s_ncand, 1);
                if (p < CAND_CAP) s_cand_idx[p] = i;
            }
        }
        atomicAdd(&s_ncert, local_cert);
    }
    __syncthreads();

    const int ncand = min(s_ncand, CAND_CAP);
    const int slots = K_TOP - s_ncert;

    if (ncand > 0) {
        for (int k = tid; k < ACT; k += TPB)
            s_x[k] = x[(size_t)row * ACT + k] - b_dec[k];
        __syncthreads();

        for (int c = wid; c < ncand; c += 32) {
            const int m = s_cand_idx[c];
            const float* w = &W_enc[(size_t)m * ACT];
            double acc = 0.0;
            const int k0 = lane * (ACT / 32);
#pragma unroll 8
            for (int k = k0; k < k0 + ACT / 32; k++)
                acc = fma((double)s_x[k], (double)__ldg(&w[k]), acc);
#pragma unroll
            for (int off = 16; off; off >>= 1)
                acc += __shfl_down_sync(FULL, acc, off);
            if (lane == 0) {
                double v = acc + (double)__ldg(&b_enc[m]);
                s_cand_val[c] = v > 0.0 ? v : 0.0;
            }
        }
        __syncthreads();

        if (tid < ncand) {
            const double vi = s_cand_val[tid];
            const int ii = s_cand_idx[tid];
            int r = 0;
            for (int j = 0; j < ncand; j++) {
                double vj = s_cand_val[j];
                if (vj > vi || (vj == vi && s_cand_idx[j] < ii)) r++;
            }
            if (r < slots) atomicOr(&s_selmask[ii >> 5], 1u << (ii & 31));
        }
        __syncthreads();
    }

#pragma unroll 4
    for (int c = 0; c < NCHUNK; c++) {
        int i = c * TPB + tid;
        bool sel = (su16[i] >= ub) ||
                   ((s_selmask[i >> 5] >> (i & 31)) & 1u);
        unsigned b = __ballot_sync(FULL, sel);
        if (lane == 0) s_cntf[c * 32 + wid] = __popc(b);
    }
    __syncthreads();

    {
        int j = wid * 32 + lane;
        int a = s_cntf[j];
        int s = a;
#pragma unroll
        for (int off = 1; off < 32; off <<= 1) {
            int t = __shfl_up_sync(FULL, s, off);
            if (lane >= off) s += t;
        }
        s_excl[j] = s - a;
        if (lane == 31) s_wtot[wid] = s;
    }
    __syncthreads();
    if (wid == 0) {
        int v = s_wtot[lane];
        int s = v;
#pragma unroll
        for (int off = 1; off < 32; off <<= 1) {
            int t = __shfl_up_sync(FULL, s, off);
            if (lane >= off) s += t;
        }
        s_wbase[lane] = s - v;
    }
    __syncthreads();

    const unsigned lmask = (1u << lane) - 1u;
#pragma unroll 4
    for (int c = 0; c < NCHUNK; c++) {
        int i = c * TPB + tid;
        unsigned u = su16[i];
        bool sel = (u >= ub) || ((s_selmask[i >> 5] >> (i & 31)) & 1u);
        unsigned b = __ballot_sync(FULL, sel);
        float uv = __half2float(__ushort_as_half((unsigned short)u));
        zr[i] = sel ? uv : 0.f;
        if (sel) {
            int j = c * 32 + wid;
            int slot = s_wbase[j >> 5] + s_excl[j] + __popc(b & lmask);
            g_idxs[row * K_TOP + slot] = i;
            g_vals[row * K_TOP + slot] = uv;
        }
    }
}

// ---------------- decode: x_hat = sum_k vals * W_decTh[idx] + b_dec ------
__global__ void __launch_bounds__(256)
decode_kernel(const float* __restrict__ b_dec, float* __restrict__ xhat) {
    __shared__ int s_idx[K_TOP];
    __shared__ float s_val[K_TOP];
    const int row = blockIdx.x;
    const int tid = threadIdx.x;
    if (tid < K_TOP) {
        s_idx[tid] = g_idxs[row * K_TOP + tid];
        s_val[tid] = g_vals[row * K_TOP + tid];
    }
    __syncthreads();
    const int d0 = tid * 8;
    float a[8];
#pragma unroll
    for (int j = 0; j < 8; j += 4) {
        float4 b4 = *(const float4*)&b_dec[d0 + j];
        a[j] = b4.x; a[j + 1] = b4.y; a[j + 2] = b4.z; a[j + 3] = b4.w;
    }
#pragma unroll 4
    for (int k = 0; k < K_TOP; k++) {
        const __half2* w = (const __half2*)&g_WdecTh[(size_t)s_idx[k] * ACT + d0];
        float v = s_val[k];
#pragma unroll
        for (int j = 0; j < 4; j++) {
            float2 f = __half22float2(w[j]);
            a[2 * j]     += v * f.x;
            a[2 * j + 1] += v * f.y;
        }
    }
    *(float4*)&xhat[(size_t)row * ACT + d0] =
        make_float4(a[0], a[1], a[2], a[3]);
    *(float4*)&xhat[(size_t)row * ACT + d0 + 4] =
        make_float4(a[4], a[5], a[6], a[7]);
}

// ---------------- launch ----------------
extern "C" void kernel_launch(void* const* d_in, const int* in_sizes, int n_in,
                              void* d_out, int out_size) {
    (void)in_sizes; (void)n_in; (void)out_size;
    const float* x     = (const float*)d_in[0];
    const float* W_enc = (const float*)d_in[1];
    const float* b_enc = (const float*)d_in[2];
    const float* W_dec = (const float*)d_in[3];
    const float* b_dec = (const float*)d_in[4];
    float* xhat = (float*)d_out;
    float* z    = xhat + (size_t)BATCH * ACT;

    prep_a_kernel<<<(BATCH * (size_t)ACT) / 1024, 256>>>(x, b_dec);
    prep_b_kernel<<<(DICT * (size_t)ACT) / 1024, 256>>>(W_enc);
    transpose_kernel<<<dim3(DICT / 32, ACT / 32), dim3(32, 8)>>>(W_dec);

    cudaFuncSetAttribute(encode_gemm_kernel,
                         cudaFuncAttributeMaxDynamicSharedMemorySize, GEMM_SMEM);
    encode_gemm_kernel<<<dim3(BATCH / BM, DICT / BN), 256, GEMM_SMEM>>>(b_enc);

    cudaFuncSetAttribute(topk_kernel,
                         cudaFuncAttributeMaxDynamicSharedMemorySize, DICT * 2);
    topk_kernel<<<BATCH, TPB, DICT * 2>>>(x, W_enc, b_enc, b_dec, z);

    decode_kernel<<<BATCH, 256>>>(b_dec, xhat);
}

// round 16
// speedup vs baseline: 1.2613x; 1.0014x over previous
#include <cuda_runtime.h>
#include <cuda_fp16.h>
#include <cstdint>

#define BATCH 4096
#define ACT   2048
#define DICT  32768
#define K_TOP 64
#define EPS   5e-3f
#define CAND_CAP 256

// ---------------- device scratch (static, no allocations) ----------------
__device__ __half g_Af[(size_t)BATCH * ACT];
__device__ __half g_Bf[(size_t)DICT * ACT];
__device__ __half g_WdecTh[(size_t)DICT * ACT];   // [DICT][ACT] fp16
__device__ __half g_P[(size_t)BATCH * DICT];      // pre_act scratch, fp16 (>=0)
__device__ float  g_vals[BATCH * K_TOP];
__device__ int    g_idxs[BATCH * K_TOP];

// ---- streams/events for graph-level fork/join (created pre-capture) ----
struct GraphRes {
    cudaStream_t sB, sT;
    cudaEvent_t eFork, eB, eT;
    GraphRes() {
        cudaStreamCreateWithFlags(&sB, cudaStreamNonBlocking);
        cudaStreamCreateWithFlags(&sT, cudaStreamNonBlocking);
        cudaEventCreateWithFlags(&eFork, cudaEventDisableTiming);
        cudaEventCreateWithFlags(&eB, cudaEventDisableTiming);
        cudaEventCreateWithFlags(&eT, cudaEventDisableTiming);
    }
};
static GraphRes g_res;

// ---------------- prep: fp32 -> fp16 ----------------
__global__ void prep_a_kernel(const float* __restrict__ x,
                              const float* __restrict__ b_dec) {
    size_t i4 = ((size_t)blockIdx.x * blockDim.x + threadIdx.x) * 4;
    float4 v = *(const float4*)&x[i4];
    int c = (int)(i4 & (ACT - 1));
    float4 b = *(const float4*)&b_dec[c];
    __half2* o = (__half2*)&g_Af[i4];
    o[0] = __floats2half2_rn(v.x - b.x, v.y - b.y);
    o[1] = __floats2half2_rn(v.z - b.z, v.w - b.w);
}

__global__ void prep_b_kernel(const float* __restrict__ W) {
    size_t i4 = ((size_t)blockIdx.x * blockDim.x + threadIdx.x) * 4;
    float4 v = *(const float4*)&W[i4];
    __half2* o = (__half2*)&g_Bf[i4];
    o[0] = __floats2half2_rn(v.x, v.y);
    o[1] = __floats2half2_rn(v.z, v.w);
}

// ---------------- transpose W_dec [ACT][DICT] -> g_WdecTh [DICT][ACT] ----
__global__ void transpose_kernel(const float* __restrict__ W) {
    __shared__ float tile[32][33];
    int bx = blockIdx.x * 32;
    int by = blockIdx.y * 32;
    int tx = threadIdx.x, ty = threadIdx.y;
#pragma unroll
    for (int j = 0; j < 32; j += 8)
        tile[ty + j][tx] = W[(size_t)(by + ty + j) * DICT + bx + tx];
    __syncthreads();
#pragma unroll
    for (int j = 0; j < 32; j += 8)
        g_WdecTh[(size_t)(bx + ty + j) * ACT + by + tx] =
            __float2half(tile[tx][ty + j]);
}

// ---------------- encode GEMM -> fp16 pre_act scratch (R11 config) -------
#define BM 128
#define BN 128
#define BK 64
#define SSTR 72
#define STAGE_ELEMS (128 * SSTR)
#define NSTAGE 3
#define GEMM_SMEM (NSTAGE * 2 * STAGE_ELEMS * 2)   // 110592 B; x2 CTA = 216KB
#define PST 136

__device__ __forceinline__ void cp16(unsigned saddr, const void* g) {
    asm volatile("cp.async.cg.shared.global [%0], [%1], 16;\n" ::"r"(saddr), "l"(g));
}

#define LDSM4(r, a)                                                          \
    asm volatile(                                                            \
        "ldmatrix.sync.aligned.m8n8.x4.shared.b16 {%0,%1,%2,%3}, [%4];"      \
        : "=r"((r)[0]), "=r"((r)[1]), "=r"((r)[2]), "=r"((r)[3])             \
        : "r"(a))

__device__ __forceinline__ void mma_f16(float* c, const uint32_t* a,
                                        const uint32_t* b) {
    asm volatile(
        "mma.sync.aligned.m16n8k16.row.col.f32.f16.f16.f32 "
        "{%0,%1,%2,%3},{%4,%5,%6,%7},{%8,%9},{%0,%1,%2,%3};\n"
        : "+f"(c[0]), "+f"(c[1]), "+f"(c[2]), "+f"(c[3])
        : "r"(a[0]), "r"(a[1]), "r"(a[2]), "r"(a[3]), "r"(b[0]), "r"(b[1]));
}

__global__ void __launch_bounds__(256, 2)
encode_gemm_kernel(const float* __restrict__ b_enc) {
    extern __shared__ __align__(16) __half sm[];

    const int tid = threadIdx.x;
    const int by = blockIdx.x * BM;
    const int bx = blockIdx.y * BN;
    const int warp = tid >> 5, lane = tid & 31;
    const int wm = (warp & 3) * 32;
    const int wn = (warp >> 2) * 64;
    const int g = lane >> 2, tig = lane & 3;

    const unsigned uS = (unsigned)__cvta_generic_to_shared(sm);

    const int aRow = wm + (lane & 15);
    const int aCol = (lane & 16) >> 1;
    const int bRow = wn + (lane & 7) + ((lane & 16) >> 1);
    const int bCol = lane & 8;

    float acc[2][8][4];
#pragma unroll
    for (int mi = 0; mi < 2; mi++)
#pragma unroll
        for (int ni = 0; ni < 8; ni++)
#pragma unroll
            for (int q = 0; q < 4; q++) acc[mi][ni][q] = 0.f;

    const int KT = ACT / BK;

#define LOAD_STAGE(stage, kt)                                                  \
    {                                                                          \
        const int koff = (kt) * BK;                                            \
        _Pragma("unroll")                                                      \
        for (int r = 0; r < 4; r++) {                                          \
            int id = tid + r * 256;                                            \
            int row = id >> 3;                                                 \
            int ch = (id & 7) * 8;                                             \
            unsigned sa =                                                      \
                (unsigned)(((stage) * 2 * STAGE_ELEMS + row * SSTR + ch) * 2); \
            cp16(uS + sa, &g_Af[(size_t)(by + row) * ACT + koff + ch]);        \
            cp16(uS + sa + STAGE_ELEMS * 2,                                    \
                 &g_Bf[(size_t)(bx + row) * ACT + koff + ch]);                 \
        }                                                                      \
    }

    LOAD_STAGE(0, 0);
    asm volatile("cp.async.commit_group;\n");
    LOAD_STAGE(1, 1);
    asm volatile("cp.async.commit_group;\n");

    int cur = 0, nxt = 2;
    for (int kt = 0; kt < KT; kt++) {
        if (kt + 2 < KT) {
            asm volatile("cp.async.wait_group 1;\n");
        } else {
            asm volatile("cp.async.wait_group 0;\n");
        }
        __syncthreads();

        if (kt + 2 < KT) {
            LOAD_STAGE(nxt, kt + 2);
            asm volatile("cp.async.commit_group;\n");
        }

        const unsigned uA = uS + (unsigned)(cur * 2 * STAGE_ELEMS * 2);
        const unsigned uB = uA + STAGE_ELEMS * 2;
#pragma unroll
        for (int ks = 0; ks < 4; ks++) {
            const int kcol = ks * 16;
            uint32_t af[2][4];
#pragma unroll
            for (int mi = 0; mi < 2; mi++) {
                unsigned ad =
                    uA + (unsigned)(((aRow + mi * 16) * SSTR + kcol + aCol) * 2);
                LDSM4(af[mi], ad);
            }
            uint32_t bf[8][2];
#pragma unroll
            for (int p = 0; p < 4; p++) {
                unsigned bd =
                    uB + (unsigned)(((bRow + p * 16) * SSTR + kcol + bCol) * 2);
                uint32_t r[4];
                LDSM4(r, bd);
                bf[2 * p][0] = r[0];
                bf[2 * p][1] = r[1];
                bf[2 * p + 1][0] = r[2];
                bf[2 * p + 1][1] = r[3];
            }
#pragma unroll
            for (int ni = 0; ni < 8; ni++)
#pragma unroll
                for (int mi = 0; mi < 2; mi++)
                    mma_f16(acc[mi][ni], af[mi], bf[ni]);
        }
        cur = (cur == 2) ? 0 : cur + 1;
        nxt = (nxt == 2) ? 0 : nxt + 1;
    }

    __syncthreads();
#pragma unroll
    for (int mi = 0; mi < 2; mi++) {
        int lr = wm + mi * 16 + g;
#pragma unroll
        for (int ni = 0; ni < 8; ni++) {
            int lc = wn + ni * 8 + tig * 2;
            float be0 = __ldg(&b_enc[bx + lc]);
            float be1 = __ldg(&b_enc[bx + lc + 1]);
            *(__half2*)&sm[lr * PST + lc] = __floats2half2_rn(
                fmaxf(acc[mi][ni][0] + be0, 0.f), fmaxf(acc[mi][ni][1] + be1, 0.f));
            *(__half2*)&sm[(lr + 8) * PST + lc] = __floats2half2_rn(
                fmaxf(acc[mi][ni][2] + be0, 0.f), fmaxf(acc[mi][ni][3] + be1, 0.f));
        }
    }
    __syncthreads();
#pragma unroll
    for (int i = tid; i < 2048; i += 256) {
        int r = i >> 4, ch = (i & 15) * 8;
        uint4 v = *(const uint4*)&sm[r * PST + ch];
        *(uint4*)&g_P[(size_t)(by + r) * DICT + bx + ch] = v;
    }
}

// ---------------- per-row top-K in fp16 bit domain -----------------------
#define TPB 1024
#define NCHUNK (DICT / TPB)    // 32

__global__ void __launch_bounds__(TPB, 2) topk_kernel(
    const float* __restrict__ x, const float* __restrict__ W_enc,
    const float* __restrict__ b_enc, const float* __restrict__ b_dec,
    float* __restrict__ z) {
    extern __shared__ __align__(16) unsigned short su16[];   // DICT u16 (64 KB)
    __shared__ unsigned s_selmask[DICT / 32];
    __shared__ float s_x[ACT];
    __shared__ unsigned s_hist[256];
    __shared__ unsigned s_gsum[8];
    __shared__ unsigned s_prefix, s_ub, s_lb;
    __shared__ int s_remaining;
    __shared__ int s_ncand, s_ncert;
    __shared__ int s_cand_idx[CAND_CAP];
    __shared__ double s_cand_val[CAND_CAP];
    __shared__ int s_cntf[NCHUNK * 32];
    __shared__ int s_excl[NCHUNK * 32];
    __shared__ int s_wtot[32], s_wbase[32];

    const unsigned FULL = 0xffffffffu;
    const int row = blockIdx.x;
    const int tid = threadIdx.x;
    const int lane = tid & 31, wid = tid >> 5;
    float* zr = z + (size_t)row * DICT;

    {
        const uint4* gp = (const uint4*)(g_P + (size_t)row * DICT);
        uint4* s4 = (uint4*)su16;
#pragma unroll
        for (int i = tid; i < DICT / 8; i += TPB) s4[i] = gp[i];
    }
    for (int i = tid; i < DICT / 32; i += TPB) s_selmask[i] = 0u;
    if (tid == 0) { s_prefix = 0u; s_remaining = K_TOP; s_ncand = 0; s_ncert = 0; }
    __syncthreads();

#pragma unroll
    for (int shift = 8; shift >= 0; shift -= 8) {
        if (tid < 256) s_hist[tid] = 0u;
        __syncthreads();
        unsigned pfx = s_prefix;
        for (int i = tid; i < DICT; i += TPB) {
            unsigned u = su16[i];
            bool ok = (u != 0u) &&
                      ((shift == 8) ? true : ((u >> 8) == (pfx >> 8)));
            if (ok) atomicAdd(&s_hist[(u >> shift) & 255u], 1u);
        }
        __syncthreads();
        if (tid < 256) {
            unsigned v = s_hist[tid];
#pragma unroll
            for (int off = 16; off; off >>= 1)
                v += __shfl_down_sync(FULL, v, off);
            if (lane == 0) s_gsum[tid >> 5] = v;
        }
        __syncthreads();
        if (tid == 0) {
            int rem = s_remaining;
            unsigned acc = 0;
            int grp = 7;
            for (; grp > 0; grp--) {
                if (acc + s_gsum[grp] >= (unsigned)rem) break;
                acc += s_gsum[grp];
            }
            int b = grp * 32 + 31;
            for (; b > grp * 32; b--) {
                if (acc + s_hist[b] >= (unsigned)rem) break;
                acc += s_hist[b];
            }
            s_prefix = pfx | ((unsigned)b << shift);
            s_remaining = rem - (int)acc;
        }
        __syncthreads();
    }

    if (tid == 0) {
        float Tf = __half2float(__ushort_as_half((unsigned short)s_prefix));
        float hi = Tf + EPS;
        float lo = Tf - EPS;
        __half hh = __float2half_ru(hi);
        unsigned hb = (unsigned)__half_as_ushort(hh);
        s_ub = (__half2float(hh) > hi) ? hb : hb + 1;
        __half hl = __float2half_ru(fmaxf(lo, 0.f));
        s_lb = (unsigned)__half_as_ushort(hl);
    }
    __syncthreads();
    const unsigned ub = s_ub, lb = s_lb;

    {
        int local_cert = 0;
        for (int i = tid; i < DICT; i += TPB) {
            unsigned u = su16[i];
            if (u >= ub) {
                local_cert++;
            } else if (u >= lb) {
                int p = atomicAdd(&s_ncand, 1);
                if (p < CAND_CAP) s_cand_idx[p] = i;
            }
        }
        atomicAdd(&s_ncert, local_cert);
    }
    __syncthreads();

    const int ncand = min(s_ncand, CAND_CAP);
    const int slots = K_TOP - s_ncert;

    if (ncand > 0) {
        for (int k = tid; k < ACT; k += TPB)
            s_x[k] = x[(size_t)row * ACT + k] - b_dec[k];
        __syncthreads();

        for (int c = wid; c < ncand; c += 32) {
            const int m = s_cand_idx[c];
            const float* w = &W_enc[(size_t)m * ACT];
            double acc = 0.0;
            const int k0 = lane * (ACT / 32);
#pragma unroll 8
            for (int k = k0; k < k0 + ACT / 32; k++)
                acc = fma((double)s_x[k], (double)__ldg(&w[k]), acc);
#pragma unroll
            for (int off = 16; off; off >>= 1)
                acc += __shfl_down_sync(FULL, acc, off);
            if (lane == 0) {
                double v = acc + (double)__ldg(&b_enc[m]);
                s_cand_val[c] = v > 0.0 ? v : 0.0;
            }
        }
        __syncthreads();

        if (tid < ncand) {
            const double vi = s_cand_val[tid];
            const int ii = s_cand_idx[tid];
            int r = 0;
            for (int j = 0; j < ncand; j++) {
                double vj = s_cand_val[j];
                if (vj > vi || (vj == vi && s_cand_idx[j] < ii)) r++;
            }
            if (r < slots) atomicOr(&s_selmask[ii >> 5], 1u << (ii & 31));
        }
        __syncthreads();
    }

#pragma unroll 4
    for (int c = 0; c < NCHUNK; c++) {
        int i = c * TPB + tid;
        bool sel = (su16[i] >= ub) ||
                   ((s_selmask[i >> 5] >> (i & 31)) & 1u);
        unsigned b = __ballot_sync(FULL, sel);
        if (lane == 0) s_cntf[c * 32 + wid] = __popc(b);
    }
    __syncthreads();

    {
        int j = wid * 32 + lane;
        int a = s_cntf[j];
        int s = a;
#pragma unroll
        for (int off = 1; off < 32; off <<= 1) {
            int t = __shfl_up_sync(FULL, s, off);
            if (lane >= off) s += t;
        }
        s_excl[j] = s - a;
        if (lane == 31) s_wtot[wid] = s;
    }
    __syncthreads();
    if (wid == 0) {
        int v = s_wtot[lane];
        int s = v;
#pragma unroll
        for (int off = 1; off < 32; off <<= 1) {
            int t = __shfl_up_sync(FULL, s, off);
            if (lane >= off) s += t;
        }
        s_wbase[lane] = s - v;
    }
    __syncthreads();

    const unsigned lmask = (1u << lane) - 1u;
#pragma unroll 4
    for (int c = 0; c < NCHUNK; c++) {
        int i = c * TPB + tid;
        unsigned u = su16[i];
        bool sel = (u >= ub) || ((s_selmask[i >> 5] >> (i & 31)) & 1u);
        unsigned b = __ballot_sync(FULL, sel);
        float uv = __half2float(__ushort_as_half((unsigned short)u));
        zr[i] = sel ? uv : 0.f;
        if (sel) {
            int j = c * 32 + wid;
            int slot = s_wbase[j >> 5] + s_excl[j] + __popc(b & lmask);
            g_idxs[row * K_TOP + slot] = i;
            g_vals[row * K_TOP + slot] = uv;
        }
    }
}

// ---------------- decode: x_hat = sum_k vals * W_decTh[idx] + b_dec ------
__global__ void __launch_bounds__(256)
decode_kernel(const float* __restrict__ b_dec, float* __restrict__ xhat) {
    __shared__ int s_idx[K_TOP];
    __shared__ float s_val[K_TOP];
    const int row = blockIdx.x;
    const int tid = threadIdx.x;
    if (tid < K_TOP) {
        s_idx[tid] = g_idxs[row * K_TOP + tid];
        s_val[tid] = g_vals[row * K_TOP + tid];
    }
    __syncthreads();
    const int d0 = tid * 8;
    float a[8];
#pragma unroll
    for (int j = 0; j < 8; j += 4) {
        float4 b4 = *(const float4*)&b_dec[d0 + j];
        a[j] = b4.x; a[j + 1] = b4.y; a[j + 2] = b4.z; a[j + 3] = b4.w;
    }
#pragma unroll 4
    for (int k = 0; k < K_TOP; k++) {
        const __half2* w = (const __half2*)&g_WdecTh[(size_t)s_idx[k] * ACT + d0];
        float v = s_val[k];
#pragma unroll
        for (int j = 0; j < 4; j++) {
            float2 f = __half22float2(w[j]);
            a[2 * j]     += v * f.x;
            a[2 * j + 1] += v * f.y;
        }
    }
    *(float4*)&xhat[(size_t)row * ACT + d0] =
        make_float4(a[0], a[1], a[2], a[3]);
    *(float4*)&xhat[(size_t)row * ACT + d0 + 4] =
        make_float4(a[4], a[5], a[6], a[7]);
}

// ---------------- launch: forked graph (prep_b, transpose overlap) -------
extern "C" void kernel_launch(void* const* d_in, const int* in_sizes, int n_in,
                              void* d_out, int out_size) {
    (void)in_sizes; (void)n_in; (void)out_size;
    const float* x     = (const float*)d_in[0];
    const float* W_enc = (const float*)d_in[1];
    const float* b_enc = (const float*)d_in[2];
    const float* W_dec = (const float*)d_in[3];
    const float* b_dec = (const float*)d_in[4];
    float* xhat = (float*)d_out;
    float* z    = xhat + (size_t)BATCH * ACT;

    cudaFuncSetAttribute(encode_gemm_kernel,
                         cudaFuncAttributeMaxDynamicSharedMemorySize, GEMM_SMEM);
    cudaFuncSetAttribute(topk_kernel,
                         cudaFuncAttributeMaxDynamicSharedMemorySize, DICT * 2);

    // fork: side streams branch off the main (captured) stream
    cudaEventRecord(g_res.eFork, 0);
    cudaStreamWaitEvent(g_res.sB, g_res.eFork, 0);
    cudaStreamWaitEvent(g_res.sT, g_res.eFork, 0);

    prep_a_kernel<<<(BATCH * (size_t)ACT) / 1024, 256>>>(x, b_dec);
    prep_b_kernel<<<(DICT * (size_t)ACT) / 1024, 256, 0, g_res.sB>>>(W_enc);
    transpose_kernel<<<dim3(DICT / 32, ACT / 32), dim3(32, 8), 0, g_res.sT>>>(W_dec);

    // join prep_b before GEMM (GEMM needs g_Af + g_Bf)
    cudaEventRecord(g_res.eB, g_res.sB);
    cudaStreamWaitEvent(0, g_res.eB, 0);

    encode_gemm_kernel<<<dim3(BATCH / BM, DICT / BN), 256, GEMM_SMEM>>>(b_enc);
    topk_kernel<<<BATCH, TPB, DICT * 2>>>(x, W_enc, b_enc, b_dec, z);

    // join transpose before decode (decode needs g_WdecTh)
    cudaEventRecord(g_res.eT, g_res.sT);
    cudaStreamWaitEvent(0, g_res.eT, 0);

    decode_kernel<<<BATCH, 256>>>(b_dec, xhat);
}